// round 2
// baseline (speedup 1.0000x reference)
#include <cuda_runtime.h>
#include <cuda_bf16.h>
#include <math.h>

// ----------------------------------------------------------------------------
// SimpleGAT: 2-layer GAT (PyG GATConv semantics, self-loops added)
//   L1: in 256 -> 4 heads x 64, concat, relu
//   L2: 256 -> 1 head x 40, mean(=identity), log_softmax
// N=10000, E=320000 (+N self loops)
// edge_index arrives as int32 (JAX x64 disabled downgrades int64 -> int32).
// ----------------------------------------------------------------------------

#define MAXN 10000
#define MAXE 320000
#define MAXET (MAXE + MAXN)

#define IN_DIM 256
#define H1_DIM 256          // heads*hidden = 4*64
#define HEADS 4
#define HID 64
#define OUT_DIM 40

// ------------------------------ scratch ------------------------------------
__device__ float g_h1[MAXN * H1_DIM];     // x @ W1
__device__ float g_out1[MAXN * H1_DIM];   // layer-1 aggregation / hrelu (in-place)
__device__ float g_as1[MAXN * HEADS];
__device__ float g_ad1[MAXN * HEADS];
__device__ float g_m1[MAXN * HEADS];
__device__ float g_s1[MAXN * HEADS];
__device__ float g_ex1[MAXET * HEADS];

__device__ float g_h2[MAXN * OUT_DIM];
__device__ float g_as2[MAXN];
__device__ float g_ad2[MAXN];
__device__ float g_m2[MAXN];
__device__ float g_s2[MAXN];
__device__ float g_ex2[MAXET];

// ------------------------------ helpers ------------------------------------
__device__ __forceinline__ void atomicMaxFloat(float* addr, float v) {
    if (v >= 0.f) atomicMax((int*)addr, __float_as_int(v));
    else          atomicMin((unsigned int*)addr, __float_as_uint(v));
}

__device__ __forceinline__ void edge_sd(const int* __restrict__ ei, int E,
                                        int e, int& s, int& d) {
    if (e < E) { s = ei[e]; d = ei[E + e]; }
    else       { s = d = e - E; }   // self loop
}

// ------------------------------ init ----------------------------------------
__global__ void k_init(float* __restrict__ out, int N) {
    int idx = blockIdx.x * blockDim.x + threadIdx.x;
    if (idx < N * H1_DIM) g_out1[idx] = 0.f;
    if (idx < N * OUT_DIM) out[idx] = 0.f;
    if (idx < N * HEADS) { g_s1[idx] = 0.f; g_m1[idx] = -INFINITY; }
    if (idx < N)         { g_s2[idx] = 0.f; g_m2[idx] = -INFINITY; }
}

// ------------------------------ GEMM1: [N,256]x[256,256] --------------------
// 64x64 tile, BK=16, 256 threads, 4x4 per thread
__global__ void k_gemm1(const float* __restrict__ A, const float* __restrict__ B,
                        int M) {
    const int K = IN_DIM, NC = H1_DIM;
    __shared__ float As[64][16];
    __shared__ float Bs[16][64 + 1];
    int tid = threadIdx.x;
    int tx = tid & 15, ty = tid >> 4;
    int rowBase = blockIdx.y * 64;
    int colBase = blockIdx.x * 64;
    float acc[4][4] = {};
    for (int k0 = 0; k0 < K; k0 += 16) {
#pragma unroll
        for (int i = 0; i < 4; i++) {
            int lin = tid + i * 256;
            int r = lin >> 4, c = lin & 15;
            int gr = rowBase + r;
            As[r][c] = (gr < M) ? A[gr * K + k0 + c] : 0.f;
        }
#pragma unroll
        for (int i = 0; i < 4; i++) {
            int lin = tid + i * 256;
            int r = lin >> 6, c = lin & 63;
            Bs[r][c] = B[(k0 + r) * NC + colBase + c];
        }
        __syncthreads();
#pragma unroll
        for (int k = 0; k < 16; k++) {
            float a[4], b[4];
#pragma unroll
            for (int i = 0; i < 4; i++) a[i] = As[ty * 4 + i][k];
#pragma unroll
            for (int j = 0; j < 4; j++) b[j] = Bs[k][tx * 4 + j];
#pragma unroll
            for (int i = 0; i < 4; i++)
#pragma unroll
                for (int j = 0; j < 4; j++) acc[i][j] = fmaf(a[i], b[j], acc[i][j]);
        }
        __syncthreads();
    }
#pragma unroll
    for (int i = 0; i < 4; i++) {
        int gr = rowBase + ty * 4 + i;
        if (gr < M)
#pragma unroll
            for (int j = 0; j < 4; j++)
                g_h1[gr * NC + colBase + tx * 4 + j] = acc[i][j];
    }
}

// --------------------- per-node attention logits, layer 1 -------------------
__global__ void k_alpha1(const float* __restrict__ att_s,
                         const float* __restrict__ att_d, int N) {
    int idx = blockIdx.x * blockDim.x + threadIdx.x;
    if (idx >= N * HEADS) return;
    int n = idx >> 2, h = idx & 3;
    const float* hp = &g_h1[n * H1_DIM + h * HID];
    float ss = 0.f, sd = 0.f;
#pragma unroll 8
    for (int k = 0; k < HID; k++) {
        float v = hp[k];
        ss = fmaf(v, att_s[h * HID + k], ss);
        sd = fmaf(v, att_d[h * HID + k], sd);
    }
    g_as1[idx] = ss;
    g_ad1[idx] = sd;
}

// --------------------- edge pass 1: e + segment max -------------------------
__global__ void k_edge_e1(const int* __restrict__ ei, int E, int ET) {
    int e = blockIdx.x * blockDim.x + threadIdx.x;
    if (e >= ET) return;
    int s, d;
    edge_sd(ei, E, e, s, d);
    float4 as = *(const float4*)&g_as1[s * HEADS];
    float4 ad = *(const float4*)&g_ad1[d * HEADS];
    float v[4] = {as.x + ad.x, as.y + ad.y, as.z + ad.z, as.w + ad.w};
#pragma unroll
    for (int h = 0; h < HEADS; h++) {
        float t = v[h];
        t = (t > 0.f) ? t : 0.2f * t;      // leaky_relu
        g_ex1[e * HEADS + h] = t;
        atomicMaxFloat(&g_m1[d * HEADS + h], t);
    }
}

// --------------------- edge pass 2: exp + segment sum -----------------------
__global__ void k_edge_x1(const int* __restrict__ ei, int E, int ET) {
    int e = blockIdx.x * blockDim.x + threadIdx.x;
    if (e >= ET) return;
    int s, d;
    edge_sd(ei, E, e, s, d);
#pragma unroll
    for (int h = 0; h < HEADS; h++) {
        float v = __expf(g_ex1[e * HEADS + h] - g_m1[d * HEADS + h]);
        g_ex1[e * HEADS + h] = v;
        atomicAdd(&g_s1[d * HEADS + h], v);
    }
}

// --------------------- edge pass 3: aggregate messages ----------------------
// one block (256 threads) per edge; channel = threadIdx.x
__global__ void k_edge_agg1(const int* __restrict__ ei, int E, int ET) {
    int e = blockIdx.x;
    if (e >= ET) return;
    int s, d;
    edge_sd(ei, E, e, s, d);
    int c = threadIdx.x;
    int h = c >> 6;
    float alpha = g_ex1[e * HEADS + h] / g_s1[d * HEADS + h];
    float v = g_h1[s * H1_DIM + c] * alpha;
    atomicAdd(&g_out1[d * H1_DIM + c], v);
}

// --------------------- bias + relu (in place) --------------------------------
__global__ void k_relu1(const float* __restrict__ bias, int N) {
    int idx = blockIdx.x * blockDim.x + threadIdx.x;
    if (idx >= N * H1_DIM) return;
    float v = g_out1[idx] + bias[idx & (H1_DIM - 1)];
    g_out1[idx] = v > 0.f ? v : 0.f;
}

// --------------------- GEMM2: [N,256]x[256,40] -------------------------------
__global__ void k_gemm2(const float* __restrict__ W2, int M) {
    __shared__ float W2s[128 * OUT_DIM];   // 20 KB
    __shared__ float hr[16 * 128];         // 8 KB
    int tid = threadIdx.x;
    int rowBase = blockIdx.x * 16;
    float acc[3] = {0.f, 0.f, 0.f};
    for (int k0 = 0; k0 < H1_DIM; k0 += 128) {
        for (int idx = tid; idx < 128 * OUT_DIM; idx += 256)
            W2s[idx] = W2[k0 * OUT_DIM + idx];
        for (int idx = tid; idx < 16 * 128; idx += 256) {
            int r = idx >> 7, k = idx & 127;
            int row = rowBase + r;
            hr[idx] = (row < M) ? g_out1[row * H1_DIM + k0 + k] : 0.f;
        }
        __syncthreads();
#pragma unroll
        for (int oi = 0; oi < 3; oi++) {
            int out_idx = tid + oi * 256;
            if (out_idx < 16 * OUT_DIM) {
                int r = out_idx / OUT_DIM, c = out_idx % OUT_DIM;
                float a = acc[oi];
#pragma unroll 8
                for (int k = 0; k < 128; k++)
                    a = fmaf(hr[r * 128 + k], W2s[k * OUT_DIM + c], a);
                acc[oi] = a;
            }
        }
        __syncthreads();
    }
#pragma unroll
    for (int oi = 0; oi < 3; oi++) {
        int out_idx = tid + oi * 256;
        if (out_idx < 16 * OUT_DIM) {
            int r = out_idx / OUT_DIM, c = out_idx % OUT_DIM;
            int row = rowBase + r;
            if (row < M) g_h2[row * OUT_DIM + c] = acc[oi];
        }
    }
}

// --------------------- per-node logits, layer 2 ------------------------------
__global__ void k_alpha2(const float* __restrict__ att_s,
                         const float* __restrict__ att_d, int N) {
    int n = blockIdx.x * blockDim.x + threadIdx.x;
    if (n >= N) return;
    float ss = 0.f, sd = 0.f;
#pragma unroll
    for (int k = 0; k < OUT_DIM; k++) {
        float v = g_h2[n * OUT_DIM + k];
        ss = fmaf(v, att_s[k], ss);
        sd = fmaf(v, att_d[k], sd);
    }
    g_as2[n] = ss;
    g_ad2[n] = sd;
}

__global__ void k_edge_e2(const int* __restrict__ ei, int E, int ET) {
    int e = blockIdx.x * blockDim.x + threadIdx.x;
    if (e >= ET) return;
    int s, d;
    edge_sd(ei, E, e, s, d);
    float v = g_as2[s] + g_ad2[d];
    v = (v > 0.f) ? v : 0.2f * v;
    g_ex2[e] = v;
    atomicMaxFloat(&g_m2[d], v);
}

__global__ void k_edge_x2(const int* __restrict__ ei, int E, int ET) {
    int e = blockIdx.x * blockDim.x + threadIdx.x;
    if (e >= ET) return;
    int s, d;
    edge_sd(ei, E, e, s, d);
    float v = __expf(g_ex2[e] - g_m2[d]);
    g_ex2[e] = v;
    atomicAdd(&g_s2[d], v);
}

// 4 edges per block of 256; 64 lanes per edge, 40 active
__global__ void k_edge_agg2(const int* __restrict__ ei, int E, int ET,
                            float* __restrict__ out) {
    int e = blockIdx.x * 4 + (threadIdx.x >> 6);
    int c = threadIdx.x & 63;
    if (e >= ET || c >= OUT_DIM) return;
    int s, d;
    edge_sd(ei, E, e, s, d);
    float alpha = g_ex2[e] / g_s2[d];
    atomicAdd(&out[d * OUT_DIM + c], g_h2[s * OUT_DIM + c] * alpha);
}

// --------------------- bias2 + log_softmax (in place on d_out) --------------
__global__ void k_logsoftmax(float* __restrict__ out,
                             const float* __restrict__ bias, int N) {
    int warp = (blockIdx.x * blockDim.x + threadIdx.x) >> 5;
    int lane = threadIdx.x & 31;
    if (warp >= N) return;
    float* row = out + warp * OUT_DIM;
    float x0 = row[lane] + bias[lane];
    float x1 = (lane < OUT_DIM - 32) ? row[lane + 32] + bias[lane + 32] : -INFINITY;
    float m = fmaxf(x0, x1);
#pragma unroll
    for (int o = 16; o > 0; o >>= 1) m = fmaxf(m, __shfl_xor_sync(0xffffffffu, m, o));
    float sum = __expf(x0 - m) + ((lane < OUT_DIM - 32) ? __expf(x1 - m) : 0.f);
#pragma unroll
    for (int o = 16; o > 0; o >>= 1) sum += __shfl_xor_sync(0xffffffffu, sum, o);
    float lse = m + logf(sum);
    row[lane] = x0 - lse;
    if (lane < OUT_DIM - 32) row[lane + 32] = x1 - lse;
}

// ----------------------------------------------------------------------------
extern "C" void kernel_launch(void* const* d_in, const int* in_sizes, int n_in,
                              void* d_out, int out_size) {
    const float* x   = (const float*)d_in[0];
    const int*   ei  = (const int*)d_in[1];       // int32 edge_index [2, E]
    const float* W1  = (const float*)d_in[2];
    const float* as1 = (const float*)d_in[3];
    const float* ad1 = (const float*)d_in[4];
    const float* b1  = (const float*)d_in[5];
    const float* W2  = (const float*)d_in[6];
    const float* as2 = (const float*)d_in[7];
    const float* ad2 = (const float*)d_in[8];
    const float* b2  = (const float*)d_in[9];
    float* out = (float*)d_out;

    int N  = in_sizes[0] / IN_DIM;
    int E  = in_sizes[1] / 2;
    int ET = E + N;

    k_init<<<(N * H1_DIM + 255) / 256, 256>>>(out, N);
    {
        dim3 grid(H1_DIM / 64, (N + 63) / 64);
        k_gemm1<<<grid, 256>>>(x, W1, N);
    }
    k_alpha1<<<(N * HEADS + 255) / 256, 256>>>(as1, ad1, N);
    k_edge_e1<<<(ET + 255) / 256, 256>>>(ei, E, ET);
    k_edge_x1<<<(ET + 255) / 256, 256>>>(ei, E, ET);
    k_edge_agg1<<<ET, 256>>>(ei, E, ET);
    k_relu1<<<(N * H1_DIM + 255) / 256, 256>>>(b1, N);

    k_gemm2<<<(N + 15) / 16, 256>>>(W2, N);
    k_alpha2<<<(N + 255) / 256, 256>>>(as2, ad2, N);
    k_edge_e2<<<(ET + 255) / 256, 256>>>(ei, E, ET);
    k_edge_x2<<<(ET + 255) / 256, 256>>>(ei, E, ET);
    k_edge_agg2<<<(ET + 3) / 4, 256>>>(ei, E, ET, out);
    k_logsoftmax<<<(N + 7) / 8, 256>>>(out, b2, N);
}

// round 3
// speedup vs baseline: 2.1489x; 2.1489x over previous
#include <cuda_runtime.h>
#include <cuda_bf16.h>
#include <math.h>

// ----------------------------------------------------------------------------
// SimpleGAT, CSR-gather formulation.
//   L1: 256 -> 4x64 concat + relu ; L2: 256 -> 40, log_softmax
//   N=10000, E=320000 (+N self-loops). edge_index is int32.
// Strategy: build dst-CSR once per launch, then one block per destination node
// does online softmax over its in-edges and register-accumulates the weighted
// feature sum. No output atomics; everything L2-resident.
// ----------------------------------------------------------------------------

#define MAXN 10000
#define MAXE 320000
#define MAXET (MAXE + MAXN)

#define IN_DIM 256
#define H1_DIM 256
#define HEADS 4
#define HID 64
#define OUT_DIM 40

// ------------------------------ scratch ------------------------------------
__device__ float g_h1[MAXN * H1_DIM];     // x @ W1
__device__ float g_out1[MAXN * H1_DIM];   // relu(agg1 + bias1)
__device__ float g_as1[MAXN * HEADS];
__device__ float g_ad1[MAXN * HEADS];

__device__ float g_h2[MAXN * OUT_DIM];
__device__ float g_as2[MAXN];
__device__ float g_ad2[MAXN];

__device__ int g_deg[MAXN];
__device__ int g_rowptr[MAXN + 1];
__device__ int g_cursor[MAXN];
__device__ int g_csr_src[MAXET];

// ------------------------------ CSR build -----------------------------------
__global__ void k_deg_init(int N) {
    int i = blockIdx.x * blockDim.x + threadIdx.x;
    if (i < N) g_deg[i] = 1;   // self loop
}

__global__ void k_deg(const int* __restrict__ ei, int E) {
    int e = blockIdx.x * blockDim.x + threadIdx.x;
    if (e < E) atomicAdd(&g_deg[ei[E + e]], 1);
}

// single-block exclusive scan over g_deg -> g_rowptr / g_cursor
__global__ void k_scan(int N) {
    __shared__ int temp[1024];
    __shared__ int carry_s;
    int tid = threadIdx.x;
    if (tid == 0) carry_s = 0;
    __syncthreads();
    for (int base = 0; base < N; base += 1024) {
        int i = base + tid;
        int v = (i < N) ? g_deg[i] : 0;
        temp[tid] = v;
        __syncthreads();
#pragma unroll
        for (int off = 1; off < 1024; off <<= 1) {
            int t = (tid >= off) ? temp[tid - off] : 0;
            __syncthreads();
            temp[tid] += t;
            __syncthreads();
        }
        int carry = carry_s;
        if (i < N) {
            int excl = carry + temp[tid] - v;
            g_rowptr[i] = excl;
            g_cursor[i] = excl;
        }
        __syncthreads();
        if (tid == 1023) carry_s = carry + temp[1023];
        __syncthreads();
    }
    if (tid == 0) g_rowptr[N] = carry_s;
}

__global__ void k_scatter(const int* __restrict__ ei, int E, int ET) {
    int e = blockIdx.x * blockDim.x + threadIdx.x;
    if (e >= ET) return;
    int s, d;
    if (e < E) { s = ei[e]; d = ei[E + e]; }
    else       { s = d = e - E; }
    int pos = atomicAdd(&g_cursor[d], 1);
    g_csr_src[pos] = s;
}

// ------------------------------ GEMM1: [N,256]x[256,256] --------------------
__global__ void k_gemm1(const float* __restrict__ A, const float* __restrict__ B,
                        int M) {
    const int K = IN_DIM, NC = H1_DIM;
    __shared__ float As[64][16];
    __shared__ float Bs[16][64 + 1];
    int tid = threadIdx.x;
    int tx = tid & 15, ty = tid >> 4;
    int rowBase = blockIdx.y * 64;
    int colBase = blockIdx.x * 64;
    float acc[4][4] = {};
    for (int k0 = 0; k0 < K; k0 += 16) {
#pragma unroll
        for (int i = 0; i < 4; i++) {
            int lin = tid + i * 256;
            int r = lin >> 4, c = lin & 15;
            int gr = rowBase + r;
            As[r][c] = (gr < M) ? A[gr * K + k0 + c] : 0.f;
        }
#pragma unroll
        for (int i = 0; i < 4; i++) {
            int lin = tid + i * 256;
            int r = lin >> 6, c = lin & 63;
            Bs[r][c] = B[(k0 + r) * NC + colBase + c];
        }
        __syncthreads();
#pragma unroll
        for (int k = 0; k < 16; k++) {
            float a[4], b[4];
#pragma unroll
            for (int i = 0; i < 4; i++) a[i] = As[ty * 4 + i][k];
#pragma unroll
            for (int j = 0; j < 4; j++) b[j] = Bs[k][tx * 4 + j];
#pragma unroll
            for (int i = 0; i < 4; i++)
#pragma unroll
                for (int j = 0; j < 4; j++) acc[i][j] = fmaf(a[i], b[j], acc[i][j]);
        }
        __syncthreads();
    }
#pragma unroll
    for (int i = 0; i < 4; i++) {
        int gr = rowBase + ty * 4 + i;
        if (gr < M)
#pragma unroll
            for (int j = 0; j < 4; j++)
                g_h1[gr * NC + colBase + tx * 4 + j] = acc[i][j];
    }
}

// --------------------- per-node attention logits ----------------------------
__global__ void k_alpha1(const float* __restrict__ att_s,
                         const float* __restrict__ att_d, int N) {
    int idx = blockIdx.x * blockDim.x + threadIdx.x;
    if (idx >= N * HEADS) return;
    int n = idx >> 2, h = idx & 3;
    const float* hp = &g_h1[n * H1_DIM + h * HID];
    float ss = 0.f, sd = 0.f;
#pragma unroll 8
    for (int k = 0; k < HID; k++) {
        float v = hp[k];
        ss = fmaf(v, att_s[h * HID + k], ss);
        sd = fmaf(v, att_d[h * HID + k], sd);
    }
    g_as1[idx] = ss;
    g_ad1[idx] = sd;
}

__global__ void k_alpha2(const float* __restrict__ att_s,
                         const float* __restrict__ att_d, int N) {
    int n = blockIdx.x * blockDim.x + threadIdx.x;
    if (n >= N) return;
    float ss = 0.f, sd = 0.f;
#pragma unroll
    for (int k = 0; k < OUT_DIM; k++) {
        float v = g_h2[n * OUT_DIM + k];
        ss = fmaf(v, att_s[k], ss);
        sd = fmaf(v, att_d[k], sd);
    }
    g_as2[n] = ss;
    g_ad2[n] = sd;
}

// --------------------- fused L1 softmax + aggregate + bias + relu -----------
// one block (256 threads) per destination node
__global__ void k_agg1(const float* __restrict__ bias) {
    int n = blockIdx.x;
    int tid = threadIdx.x;
    int beg = g_rowptr[n];
    int deg = g_rowptr[n + 1] - beg;

    __shared__ float sh_m[HEADS], sh_inv[HEADS];
    __shared__ int   sh_src[64];
    __shared__ float sh_w[HEADS * 64];

    float4 ad4 = *(const float4*)&g_ad1[n * HEADS];
    const float adArr[4] = {ad4.x, ad4.y, ad4.z, ad4.w};

    // phase A: online softmax stats, warp w handles head w (warps 0..3)
    int warp = tid >> 5, lane = tid & 31;
    if (warp < HEADS) {
        float adh = adArr[warp];
        float m = -1e30f, s = 0.f;
        for (int i = lane; i < deg; i += 32) {
            int src = g_csr_src[beg + i];
            float t = g_as1[src * HEADS + warp] + adh;
            t = (t > 0.f) ? t : 0.2f * t;
            if (t > m) { s = s * __expf(m - t) + 1.f; m = t; }
            else       { s += __expf(t - m); }
        }
#pragma unroll
        for (int off = 16; off > 0; off >>= 1) {
            float m2 = __shfl_xor_sync(0xffffffffu, m, off);
            float s2 = __shfl_xor_sync(0xffffffffu, s, off);
            float mn = fmaxf(m, m2);
            s = s * __expf(m - mn) + s2 * __expf(m2 - mn);
            m = mn;
        }
        if (lane == 0) { sh_m[warp] = m; sh_inv[warp] = 1.f / s; }
    }
    __syncthreads();

    // phase B: weighted gather-accumulate
    int h = tid >> 6;
    float mh = sh_m[h], ih = sh_inv[h];  // not used directly; weights in shared
    (void)mh; (void)ih;
    float acc0 = 0.f, acc1 = 0.f, acc2 = 0.f, acc3 = 0.f;
    for (int base = 0; base < deg; base += 64) {
        int len = min(64, deg - base);
        __syncthreads();
        if (tid < len) {
            int src = g_csr_src[beg + base + tid];
            sh_src[tid] = src;
            float4 as = *(const float4*)&g_as1[src * HEADS];
            float t0 = as.x + adArr[0]; t0 = (t0 > 0.f) ? t0 : 0.2f * t0;
            float t1 = as.y + adArr[1]; t1 = (t1 > 0.f) ? t1 : 0.2f * t1;
            float t2 = as.z + adArr[2]; t2 = (t2 > 0.f) ? t2 : 0.2f * t2;
            float t3 = as.w + adArr[3]; t3 = (t3 > 0.f) ? t3 : 0.2f * t3;
            sh_w[0 * 64 + tid] = __expf(t0 - sh_m[0]) * sh_inv[0];
            sh_w[1 * 64 + tid] = __expf(t1 - sh_m[1]) * sh_inv[1];
            sh_w[2 * 64 + tid] = __expf(t2 - sh_m[2]) * sh_inv[2];
            sh_w[3 * 64 + tid] = __expf(t3 - sh_m[3]) * sh_inv[3];
        }
        __syncthreads();
        const float* wrow = &sh_w[h * 64];
        int k = 0;
        for (; k + 4 <= len; k += 4) {
            acc0 = fmaf(wrow[k + 0], g_h1[sh_src[k + 0] * H1_DIM + tid], acc0);
            acc1 = fmaf(wrow[k + 1], g_h1[sh_src[k + 1] * H1_DIM + tid], acc1);
            acc2 = fmaf(wrow[k + 2], g_h1[sh_src[k + 2] * H1_DIM + tid], acc2);
            acc3 = fmaf(wrow[k + 3], g_h1[sh_src[k + 3] * H1_DIM + tid], acc3);
        }
        for (; k < len; k++)
            acc0 = fmaf(wrow[k], g_h1[sh_src[k] * H1_DIM + tid], acc0);
    }
    float v = (acc0 + acc1) + (acc2 + acc3) + bias[tid];
    g_out1[n * H1_DIM + tid] = v > 0.f ? v : 0.f;
}

// --------------------- GEMM2: [N,256]x[256,40] -------------------------------
__global__ void k_gemm2(const float* __restrict__ W2, int M) {
    __shared__ float W2s[128 * OUT_DIM];
    __shared__ float hr[16 * 128];
    int tid = threadIdx.x;
    int rowBase = blockIdx.x * 16;
    float acc[3] = {0.f, 0.f, 0.f};
    for (int k0 = 0; k0 < H1_DIM; k0 += 128) {
        for (int idx = tid; idx < 128 * OUT_DIM; idx += 256)
            W2s[idx] = W2[k0 * OUT_DIM + idx];
        for (int idx = tid; idx < 16 * 128; idx += 256) {
            int r = idx >> 7, k = idx & 127;
            int row = rowBase + r;
            hr[idx] = (row < M) ? g_out1[row * H1_DIM + k0 + k] : 0.f;
        }
        __syncthreads();
#pragma unroll
        for (int oi = 0; oi < 3; oi++) {
            int out_idx = tid + oi * 256;
            if (out_idx < 16 * OUT_DIM) {
                int r = out_idx / OUT_DIM, c = out_idx % OUT_DIM;
                float a = acc[oi];
#pragma unroll 8
                for (int k = 0; k < 128; k++)
                    a = fmaf(hr[r * 128 + k], W2s[k * OUT_DIM + c], a);
                acc[oi] = a;
            }
        }
        __syncthreads();
    }
#pragma unroll
    for (int oi = 0; oi < 3; oi++) {
        int out_idx = tid + oi * 256;
        if (out_idx < 16 * OUT_DIM) {
            int r = out_idx / OUT_DIM, c = out_idx % OUT_DIM;
            int row = rowBase + r;
            if (row < M) g_h2[row * OUT_DIM + c] = acc[oi];
        }
    }
}

// ---- fused L2 softmax + aggregate + bias + log_softmax (block=128/dst) -----
__global__ void k_agg2(const float* __restrict__ bias, float* __restrict__ out) {
    int n = blockIdx.x;
    int tid = threadIdx.x;
    int beg = g_rowptr[n];
    int deg = g_rowptr[n + 1] - beg;

    __shared__ float sh_m, sh_inv;
    __shared__ int   sh_src[64];
    __shared__ float sh_w[64];
    __shared__ float sh_part[128];
    __shared__ float sh_row[OUT_DIM];
    __shared__ float sh_lse;

    float adn = g_ad2[n];

    // phase A: warp 0 online softmax
    if (tid < 32) {
        float m = -1e30f, s = 0.f;
        for (int i = tid; i < deg; i += 32) {
            int src = g_csr_src[beg + i];
            float t = g_as2[src] + adn;
            t = (t > 0.f) ? t : 0.2f * t;
            if (t > m) { s = s * __expf(m - t) + 1.f; m = t; }
            else       { s += __expf(t - m); }
        }
#pragma unroll
        for (int off = 16; off > 0; off >>= 1) {
            float m2 = __shfl_xor_sync(0xffffffffu, m, off);
            float s2 = __shfl_xor_sync(0xffffffffu, s, off);
            float mn = fmaxf(m, m2);
            s = s * __expf(m - mn) + s2 * __expf(m2 - mn);
            m = mn;
        }
        if (tid == 0) { sh_m = m; sh_inv = 1.f / s; }
    }
    __syncthreads();

    // phase B: two edge-slices in parallel (eo = tid>>6)
    int eo = tid >> 6, c = tid & 63;
    float acc = 0.f;
    for (int base = 0; base < deg; base += 64) {
        int len = min(64, deg - base);
        __syncthreads();
        if (tid < len) {
            int src = g_csr_src[beg + base + tid];
            sh_src[tid] = src;
            float t = g_as2[src] + adn;
            t = (t > 0.f) ? t : 0.2f * t;
            sh_w[tid] = __expf(t - sh_m) * sh_inv;
        }
        __syncthreads();
        if (c < OUT_DIM) {
            for (int k = eo; k < len; k += 2)
                acc = fmaf(sh_w[k], g_h2[sh_src[k] * OUT_DIM + c], acc);
        }
    }
    sh_part[tid] = acc;
    __syncthreads();

    // combine halves + bias, then log_softmax over the 40-wide row
    if (tid < OUT_DIM) {
        float v = sh_part[tid] + sh_part[tid + 64] + bias[tid];
        sh_row[tid] = v;
    }
    __syncthreads();
    if (tid == 0) {
        float m = -1e30f;
#pragma unroll
        for (int k = 0; k < OUT_DIM; k++) m = fmaxf(m, sh_row[k]);
        float s = 0.f;
#pragma unroll
        for (int k = 0; k < OUT_DIM; k++) s += __expf(sh_row[k] - m);
        sh_lse = m + logf(s);
    }
    __syncthreads();
    if (tid < OUT_DIM) out[n * OUT_DIM + tid] = sh_row[tid] - sh_lse;
}

// ----------------------------------------------------------------------------
extern "C" void kernel_launch(void* const* d_in, const int* in_sizes, int n_in,
                              void* d_out, int out_size) {
    const float* x   = (const float*)d_in[0];
    const int*   ei  = (const int*)d_in[1];
    const float* W1  = (const float*)d_in[2];
    const float* as1 = (const float*)d_in[3];
    const float* ad1 = (const float*)d_in[4];
    const float* b1  = (const float*)d_in[5];
    const float* W2  = (const float*)d_in[6];
    const float* as2 = (const float*)d_in[7];
    const float* ad2 = (const float*)d_in[8];
    const float* b2  = (const float*)d_in[9];
    float* out = (float*)d_out;

    int N  = in_sizes[0] / IN_DIM;
    int E  = in_sizes[1] / 2;
    int ET = E + N;

    // CSR build
    k_deg_init<<<(N + 255) / 256, 256>>>(N);
    k_deg<<<(E + 255) / 256, 256>>>(ei, E);
    k_scan<<<1, 1024>>>(N);
    k_scatter<<<(ET + 255) / 256, 256>>>(ei, E, ET);

    // layer 1
    {
        dim3 grid(H1_DIM / 64, (N + 63) / 64);
        k_gemm1<<<grid, 256>>>(x, W1, N);
    }
    k_alpha1<<<(N * HEADS + 255) / 256, 256>>>(as1, ad1, N);
    k_agg1<<<N, 256>>>(b1);

    // layer 2
    k_gemm2<<<(N + 15) / 16, 256>>>(W2, N);
    k_alpha2<<<(N + 255) / 256, 256>>>(as2, ad2, N);
    k_agg2<<<N, 128>>>(b2, out);
}

// round 4
// speedup vs baseline: 2.2371x; 1.0410x over previous
#include <cuda_runtime.h>
#include <cuda_bf16.h>
#include <math.h>

// ----------------------------------------------------------------------------
// SimpleGAT, CSR-gather formulation, vectorized (R4).
// ----------------------------------------------------------------------------

#define MAXN 10000
#define MAXE 320000
#define MAXET (MAXE + MAXN)

#define IN_DIM 256
#define H1_DIM 256
#define HEADS 4
#define HID 64
#define OUT_DIM 40

// ------------------------------ scratch ------------------------------------
__device__ __align__(16) float g_h1[MAXN * H1_DIM];
__device__ __align__(16) float g_out1[MAXN * H1_DIM];
__device__ __align__(16) float g_as1[MAXN * HEADS];
__device__ __align__(16) float g_ad1[MAXN * HEADS];

__device__ __align__(16) float g_h2[MAXN * OUT_DIM];
__device__ float g_as2[MAXN];
__device__ float g_ad2[MAXN];

__device__ int g_deg[MAXN];
__device__ int g_rowptr[MAXN + 1];
__device__ int g_cursor[MAXN];
__device__ int g_csr_src[MAXET];

__device__ __forceinline__ float lrelu(float t) { return t > 0.f ? t : 0.2f * t; }

// ------------------------------ CSR build -----------------------------------
__global__ void k_deg_init(int N) {
    int i = blockIdx.x * blockDim.x + threadIdx.x;
    if (i < N) g_deg[i] = 1;   // self loop
}

__global__ void k_deg(const int* __restrict__ ei, int E) {
    int e = blockIdx.x * blockDim.x + threadIdx.x;
    if (e < E) atomicAdd(&g_deg[ei[E + e]], 1);
}

// single-block scan: per-thread segment + warp-shuffle block scan
__global__ void k_scan(int N) {
    int tid = threadIdx.x;
    const int C = (N + 1023) >> 10;          // <= 16 for N <= 16384
    int start = tid * C;
    int local[16];
    int sum = 0;
#pragma unroll
    for (int j = 0; j < 16; j++) {
        if (j >= C) break;
        int i = start + j;
        int v = (i < N) ? g_deg[i] : 0;
        local[j] = sum;
        sum += v;
    }
    int lane = tid & 31, warp = tid >> 5;
    int inc = sum;
#pragma unroll
    for (int off = 1; off < 32; off <<= 1) {
        int t = __shfl_up_sync(0xffffffffu, inc, off);
        if (lane >= off) inc += t;
    }
    __shared__ int wtot[32];
    if (lane == 31) wtot[warp] = inc;
    __syncthreads();
    if (warp == 0) {
        int v = wtot[lane];
#pragma unroll
        for (int off = 1; off < 32; off <<= 1) {
            int t = __shfl_up_sync(0xffffffffu, v, off);
            if (lane >= off) v += t;
        }
        wtot[lane] = v;
    }
    __syncthreads();
    int carry = (warp > 0 ? wtot[warp - 1] : 0) + (inc - sum);
#pragma unroll
    for (int j = 0; j < 16; j++) {
        if (j >= C) break;
        int i = start + j;
        if (i < N) {
            int e = carry + local[j];
            g_rowptr[i] = e;
            g_cursor[i] = e;
        }
    }
    if (tid == 1023) g_rowptr[N] = wtot[31];
}

__global__ void k_scatter(const int* __restrict__ ei, int E, int ET) {
    int e = blockIdx.x * blockDim.x + threadIdx.x;
    if (e >= ET) return;
    int s, d;
    if (e < E) { s = ei[e]; d = ei[E + e]; }
    else       { s = d = e - E; }
    int pos = atomicAdd(&g_cursor[d], 1);
    g_csr_src[pos] = s;
}

// ------------------------------ GEMM1: [N,256]x[256,256] --------------------
// 128x64 tile, BK=32, 256 threads, 8x4 per thread, float4 loads
#define G1_BM 128
#define G1_BN 64
#define G1_BK 32

__global__ void k_gemm1(const float* __restrict__ A, const float* __restrict__ B,
                        int M) {
    __shared__ float As[G1_BK][G1_BM + 8];   // transposed, padded to 16B rows
    __shared__ float Bs[G1_BK][G1_BN];
    int tid = threadIdx.x;
    int tx = tid & 15;        // 16 col-groups of 4
    int ty = tid >> 4;        // 16 row-groups of 8
    int rowBase = blockIdx.y * G1_BM;
    int colBase = blockIdx.x * G1_BN;
    float acc[8][4] = {};
    for (int k0 = 0; k0 < IN_DIM; k0 += G1_BK) {
#pragma unroll
        for (int i = 0; i < 4; i++) {
            int f = tid + i * 256;            // 0..1023
            int r = f >> 3, c4 = f & 7;
            int gr = rowBase + r;
            float4 v = make_float4(0.f, 0.f, 0.f, 0.f);
            if (gr < M) v = *(const float4*)&A[gr * IN_DIM + k0 + c4 * 4];
            As[c4 * 4 + 0][r] = v.x;
            As[c4 * 4 + 1][r] = v.y;
            As[c4 * 4 + 2][r] = v.z;
            As[c4 * 4 + 3][r] = v.w;
        }
#pragma unroll
        for (int i = 0; i < 2; i++) {
            int f = tid + i * 256;            // 0..511
            int r = f >> 4, c4 = f & 15;
            *(float4*)&Bs[r][c4 * 4] =
                *(const float4*)&B[(k0 + r) * H1_DIM + colBase + c4 * 4];
        }
        __syncthreads();
#pragma unroll
        for (int k = 0; k < G1_BK; k++) {
            float4 b4 = *(const float4*)&Bs[k][tx * 4];
            float4 a0 = *(const float4*)&As[k][ty * 8];
            float4 a1 = *(const float4*)&As[k][ty * 8 + 4];
            float a[8] = {a0.x, a0.y, a0.z, a0.w, a1.x, a1.y, a1.z, a1.w};
            float b[4] = {b4.x, b4.y, b4.z, b4.w};
#pragma unroll
            for (int i = 0; i < 8; i++)
#pragma unroll
                for (int j = 0; j < 4; j++)
                    acc[i][j] = fmaf(a[i], b[j], acc[i][j]);
        }
        __syncthreads();
    }
#pragma unroll
    for (int i = 0; i < 8; i++) {
        int gr = rowBase + ty * 8 + i;
        if (gr < M)
            *(float4*)&g_h1[gr * H1_DIM + colBase + tx * 4] =
                make_float4(acc[i][0], acc[i][1], acc[i][2], acc[i][3]);
    }
}

// --------------------- per-node attention logits ----------------------------
__global__ void k_alpha1(const float* __restrict__ att_s,
                         const float* __restrict__ att_d, int N) {
    int idx = blockIdx.x * blockDim.x + threadIdx.x;
    if (idx >= N * HEADS) return;
    int n = idx >> 2, h = idx & 3;
    const float4* hp = (const float4*)&g_h1[n * H1_DIM + h * HID];
    const float4* sp = (const float4*)&att_s[h * HID];
    const float4* dp = (const float4*)&att_d[h * HID];
    float ss = 0.f, sd = 0.f;
#pragma unroll
    for (int k = 0; k < HID / 4; k++) {
        float4 v = hp[k], a = sp[k], b = dp[k];
        ss = fmaf(v.x, a.x, fmaf(v.y, a.y, fmaf(v.z, a.z, fmaf(v.w, a.w, ss))));
        sd = fmaf(v.x, b.x, fmaf(v.y, b.y, fmaf(v.z, b.z, fmaf(v.w, b.w, sd))));
    }
    g_as1[idx] = ss;
    g_ad1[idx] = sd;
}

__global__ void k_alpha2(const float* __restrict__ att_s,
                         const float* __restrict__ att_d, int N) {
    int n = blockIdx.x * blockDim.x + threadIdx.x;
    if (n >= N) return;
    float ss = 0.f, sd = 0.f;
#pragma unroll
    for (int k = 0; k < OUT_DIM; k++) {
        float v = g_h2[n * OUT_DIM + k];
        ss = fmaf(v, att_s[k], ss);
        sd = fmaf(v, att_d[k], sd);
    }
    g_as2[n] = ss;
    g_ad2[n] = sd;
}

// --------------------- fused L1 softmax + aggregate + bias + relu -----------
// one block (256 threads) per destination node; float4 channels
__device__ __forceinline__ void online_upd(float& m, float& s, float t) {
    if (t > m) { s = s * __expf(m - t) + 1.f; m = t; }
    else       { s += __expf(t - m); }
}
__device__ __forceinline__ void online_merge(float& m, float& s, float m2, float s2) {
    float mn = fmaxf(m, m2);
    s = s * __expf(m - mn) + s2 * __expf(m2 - mn);
    m = mn;
}

__global__ void k_agg1(const float* __restrict__ bias) {
    int n = blockIdx.x;
    int tid = threadIdx.x;
    int beg = g_rowptr[n];
    int deg = g_rowptr[n + 1] - beg;
    int lane = tid & 31, warp = tid >> 5;

    __shared__ float4 sh_pm[8], sh_ps[8];
    __shared__ float sh_m[HEADS], sh_inv[HEADS];
    __shared__ int   sh_src[64];
    __shared__ float sh_w[HEADS][64];
    __shared__ float sh_red[4][H1_DIM];

    float4 ad4 = *(const float4*)&g_ad1[n * HEADS];

    // phase A: 8 warps share edges, componentwise online softmax (4 heads)
    float4 m4 = make_float4(-1e30f, -1e30f, -1e30f, -1e30f);
    float4 s4 = make_float4(0.f, 0.f, 0.f, 0.f);
    for (int i = tid; i < deg; i += 256) {
        int src = g_csr_src[beg + i];
        float4 as = *(const float4*)&g_as1[src * HEADS];
        online_upd(m4.x, s4.x, lrelu(as.x + ad4.x));
        online_upd(m4.y, s4.y, lrelu(as.y + ad4.y));
        online_upd(m4.z, s4.z, lrelu(as.z + ad4.z));
        online_upd(m4.w, s4.w, lrelu(as.w + ad4.w));
    }
#pragma unroll
    for (int off = 16; off > 0; off >>= 1) {
        float4 m2, s2;
        m2.x = __shfl_xor_sync(0xffffffffu, m4.x, off);
        m2.y = __shfl_xor_sync(0xffffffffu, m4.y, off);
        m2.z = __shfl_xor_sync(0xffffffffu, m4.z, off);
        m2.w = __shfl_xor_sync(0xffffffffu, m4.w, off);
        s2.x = __shfl_xor_sync(0xffffffffu, s4.x, off);
        s2.y = __shfl_xor_sync(0xffffffffu, s4.y, off);
        s2.z = __shfl_xor_sync(0xffffffffu, s4.z, off);
        s2.w = __shfl_xor_sync(0xffffffffu, s4.w, off);
        online_merge(m4.x, s4.x, m2.x, s2.x);
        online_merge(m4.y, s4.y, m2.y, s2.y);
        online_merge(m4.z, s4.z, m2.z, s2.z);
        online_merge(m4.w, s4.w, m2.w, s2.w);
    }
    if (lane == 0) { sh_pm[warp] = m4; sh_ps[warp] = s4; }
    __syncthreads();
    if (tid == 0) {
        float4 m = sh_pm[0], s = sh_ps[0];
#pragma unroll
        for (int w = 1; w < 8; w++) {
            online_merge(m.x, s.x, sh_pm[w].x, sh_ps[w].x);
            online_merge(m.y, s.y, sh_pm[w].y, sh_ps[w].y);
            online_merge(m.z, s.z, sh_pm[w].z, sh_ps[w].z);
            online_merge(m.w, s.w, sh_pm[w].w, sh_ps[w].w);
        }
        sh_m[0] = m.x; sh_m[1] = m.y; sh_m[2] = m.z; sh_m[3] = m.w;
        sh_inv[0] = 1.f / s.x; sh_inv[1] = 1.f / s.y;
        sh_inv[2] = 1.f / s.z; sh_inv[3] = 1.f / s.w;
    }

    // phase B: 4 edge-groups x 64 float4-channels
    int g = tid >> 6, c4 = tid & 63, head = c4 >> 4;
    float4 acc = make_float4(0.f, 0.f, 0.f, 0.f);
    for (int base = 0; base < deg; base += 64) {
        int len = min(64, deg - base);
        __syncthreads();
        if (tid < len) {
            int src = g_csr_src[beg + base + tid];
            sh_src[tid] = src;
            float4 as = *(const float4*)&g_as1[src * HEADS];
            sh_w[0][tid] = __expf(lrelu(as.x + ad4.x) - sh_m[0]) * sh_inv[0];
            sh_w[1][tid] = __expf(lrelu(as.y + ad4.y) - sh_m[1]) * sh_inv[1];
            sh_w[2][tid] = __expf(lrelu(as.z + ad4.z) - sh_m[2]) * sh_inv[2];
            sh_w[3][tid] = __expf(lrelu(as.w + ad4.w) - sh_m[3]) * sh_inv[3];
        }
        __syncthreads();
        for (int k = g; k < len; k += 4) {
            float w = sh_w[head][k];
            float4 v = *(const float4*)&g_h1[sh_src[k] * H1_DIM + c4 * 4];
            acc.x = fmaf(w, v.x, acc.x);
            acc.y = fmaf(w, v.y, acc.y);
            acc.z = fmaf(w, v.z, acc.z);
            acc.w = fmaf(w, v.w, acc.w);
        }
    }
    *(float4*)&sh_red[g][c4 * 4] = acc;
    __syncthreads();
    int c = tid;
    float v = sh_red[0][c] + sh_red[1][c] + sh_red[2][c] + sh_red[3][c] + bias[c];
    g_out1[n * H1_DIM + c] = v > 0.f ? v : 0.f;
}

// --------------------- GEMM2: [N,256]x[256,40] -------------------------------
// 32 rows/block, BK=64, 256 threads
__global__ void k_gemm2(const float* __restrict__ W2, int M) {
    __shared__ float W2s[64 * OUT_DIM];     // 10 KB
    __shared__ float hr[32 * 64];           // 8 KB
    int tid = threadIdx.x;
    int rowBase = blockIdx.x * 32;
    float acc[5] = {0.f, 0.f, 0.f, 0.f, 0.f};
    for (int k0 = 0; k0 < H1_DIM; k0 += 64) {
        for (int idx = tid; idx < 64 * OUT_DIM; idx += 256)
            W2s[idx] = W2[(k0 + idx / OUT_DIM) * OUT_DIM + idx % OUT_DIM];
        for (int f = tid; f < 512; f += 256) {
            int r = f >> 4, c4 = f & 15;
            int row = rowBase + r;
            float4 v = make_float4(0.f, 0.f, 0.f, 0.f);
            if (row < M) v = *(const float4*)&g_out1[row * H1_DIM + k0 + c4 * 4];
            *(float4*)&hr[r * 64 + c4 * 4] = v;
        }
        __syncthreads();
#pragma unroll
        for (int oi = 0; oi < 5; oi++) {
            int out_idx = tid + oi * 256;
            int r = out_idx / OUT_DIM, c = out_idx % OUT_DIM;
            float a = acc[oi];
#pragma unroll 8
            for (int k = 0; k < 64; k++)
                a = fmaf(hr[r * 64 + k], W2s[k * OUT_DIM + c], a);
            acc[oi] = a;
        }
        __syncthreads();
    }
#pragma unroll
    for (int oi = 0; oi < 5; oi++) {
        int out_idx = tid + oi * 256;
        int r = out_idx / OUT_DIM, c = out_idx % OUT_DIM;
        int row = rowBase + r;
        if (row < M) g_h2[row * OUT_DIM + c] = acc[oi];
    }
}

// ---- fused L2 softmax + aggregate + bias + log_softmax (block=128/dst) -----
__global__ void k_agg2(const float* __restrict__ bias, float* __restrict__ out) {
    int n = blockIdx.x;
    int tid = threadIdx.x;
    int beg = g_rowptr[n];
    int deg = g_rowptr[n + 1] - beg;

    __shared__ float sh_m, sh_inv;
    __shared__ int   sh_src[64];
    __shared__ float sh_w[64];
    __shared__ float sh_part[128];
    __shared__ float sh_row[OUT_DIM];
    __shared__ float sh_lse;

    float adn = g_ad2[n];

    if (tid < 32) {
        float m = -1e30f, s = 0.f;
        for (int i = tid; i < deg; i += 32) {
            int src = g_csr_src[beg + i];
            online_upd(m, s, lrelu(g_as2[src] + adn));
        }
#pragma unroll
        for (int off = 16; off > 0; off >>= 1) {
            float m2 = __shfl_xor_sync(0xffffffffu, m, off);
            float s2 = __shfl_xor_sync(0xffffffffu, s, off);
            online_merge(m, s, m2, s2);
        }
        if (tid == 0) { sh_m = m; sh_inv = 1.f / s; }
    }
    __syncthreads();

    int eo = tid >> 6, c = tid & 63;
    float acc = 0.f;
    for (int base = 0; base < deg; base += 64) {
        int len = min(64, deg - base);
        __syncthreads();
        if (tid < len) {
            int src = g_csr_src[beg + base + tid];
            sh_src[tid] = src;
            sh_w[tid] = __expf(lrelu(g_as2[src] + adn) - sh_m) * sh_inv;
        }
        __syncthreads();
        if (c < OUT_DIM) {
            for (int k = eo; k < len; k += 2)
                acc = fmaf(sh_w[k], g_h2[sh_src[k] * OUT_DIM + c], acc);
        }
    }
    sh_part[tid] = acc;
    __syncthreads();

    if (tid < OUT_DIM)
        sh_row[tid] = sh_part[tid] + sh_part[tid + 64] + bias[tid];
    __syncthreads();
    if (tid == 0) {
        float m = -1e30f;
#pragma unroll
        for (int k = 0; k < OUT_DIM; k++) m = fmaxf(m, sh_row[k]);
        float s = 0.f;
#pragma unroll
        for (int k = 0; k < OUT_DIM; k++) s += __expf(sh_row[k] - m);
        sh_lse = m + logf(s);
    }
    __syncthreads();
    if (tid < OUT_DIM) out[n * OUT_DIM + tid] = sh_row[tid] - sh_lse;
}

// ----------------------------------------------------------------------------
extern "C" void kernel_launch(void* const* d_in, const int* in_sizes, int n_in,
                              void* d_out, int out_size) {
    const float* x   = (const float*)d_in[0];
    const int*   ei  = (const int*)d_in[1];
    const float* W1  = (const float*)d_in[2];
    const float* as1 = (const float*)d_in[3];
    const float* ad1 = (const float*)d_in[4];
    const float* b1  = (const float*)d_in[5];
    const float* W2  = (const float*)d_in[6];
    const float* as2 = (const float*)d_in[7];
    const float* ad2 = (const float*)d_in[8];
    const float* b2  = (const float*)d_in[9];
    float* out = (float*)d_out;

    int N  = in_sizes[0] / IN_DIM;
    int E  = in_sizes[1] / 2;
    int ET = E + N;

    // CSR build
    k_deg_init<<<(N + 255) / 256, 256>>>(N);
    k_deg<<<(E + 255) / 256, 256>>>(ei, E);
    k_scan<<<1, 1024>>>(N);
    k_scatter<<<(ET + 255) / 256, 256>>>(ei, E, ET);

    // layer 1
    {
        dim3 grid(H1_DIM / G1_BN, (N + G1_BM - 1) / G1_BM);
        k_gemm1<<<grid, 256>>>(x, W1, N);
    }
    k_alpha1<<<(N * HEADS + 255) / 256, 256>>>(as1, ad1, N);
    k_agg1<<<N, 256>>>(b1);

    // layer 2
    k_gemm2<<<(N + 31) / 32, 256>>>(W2, N);
    k_alpha2<<<(N + 255) / 256, 256>>>(as2, ad2, N);
    k_agg2<<<N, 128>>>(b2, out);
}

// round 5
// speedup vs baseline: 2.5129x; 1.1233x over previous
#include <cuda_runtime.h>
#include <cuda_bf16.h>
#include <math.h>

// ----------------------------------------------------------------------------
// SimpleGAT R5: fused-epilogue GEMMs + single-pass softmax aggregation.
// 7 kernel launches total.
// ----------------------------------------------------------------------------

#define MAXN 10000
#define MAXE 320000
#define MAXET (MAXE + MAXN)

#define IN_DIM 256
#define H1_DIM 256
#define HEADS 4
#define HID 64
#define OUT_DIM 40

// ------------------------------ scratch ------------------------------------
__device__ __align__(16) float g_h1[MAXN * H1_DIM];
__device__ __align__(16) float g_out1[MAXN * H1_DIM];
__device__ __align__(16) float g_as1[MAXN * HEADS];
__device__ __align__(16) float g_ad1[MAXN * HEADS];

__device__ __align__(16) float g_h2[MAXN * OUT_DIM];
__device__ float g_as2[MAXN];
__device__ float g_ad2[MAXN];

__device__ int g_deg[MAXN];        // static-zero; re-zeroed by k_scatter each run
__device__ int g_rowptr[MAXN + 1];
__device__ int g_cursor[MAXN];
__device__ int g_csr_src[MAXET];

__device__ __forceinline__ float lrelu(float t) { return t > 0.f ? t : 0.2f * t; }

// ------------------------------ CSR build -----------------------------------
__global__ void k_deg(const int* __restrict__ ei, int E) {
    int e = blockIdx.x * blockDim.x + threadIdx.x;
    if (e < E) atomicAdd(&g_deg[ei[E + e]], 1);
}

// single-block scan (adds +1 per node for the self loop)
__global__ void k_scan(int N) {
    int tid = threadIdx.x;
    const int C = (N + 1023) >> 10;
    int start = tid * C;
    int local[16];
    int sum = 0;
#pragma unroll
    for (int j = 0; j < 16; j++) {
        if (j >= C) break;
        int i = start + j;
        int v = (i < N) ? (g_deg[i] + 1) : 0;
        local[j] = sum;
        sum += v;
    }
    int lane = tid & 31, warp = tid >> 5;
    int inc = sum;
#pragma unroll
    for (int off = 1; off < 32; off <<= 1) {
        int t = __shfl_up_sync(0xffffffffu, inc, off);
        if (lane >= off) inc += t;
    }
    __shared__ int wtot[32];
    if (lane == 31) wtot[warp] = inc;
    __syncthreads();
    if (warp == 0) {
        int v = wtot[lane];
#pragma unroll
        for (int off = 1; off < 32; off <<= 1) {
            int t = __shfl_up_sync(0xffffffffu, v, off);
            if (lane >= off) v += t;
        }
        wtot[lane] = v;
    }
    __syncthreads();
    int carry = (warp > 0 ? wtot[warp - 1] : 0) + (inc - sum);
#pragma unroll
    for (int j = 0; j < 16; j++) {
        if (j >= C) break;
        int i = start + j;
        if (i < N) {
            int e = carry + local[j];
            g_rowptr[i] = e;
            g_cursor[i] = e;
        }
    }
    if (tid == 1023) g_rowptr[N] = wtot[31];
}

__global__ void k_scatter(const int* __restrict__ ei, int E, int ET) {
    int e = blockIdx.x * blockDim.x + threadIdx.x;
    if (e >= ET) return;
    int s, d;
    if (e < E) { s = ei[e]; d = ei[E + e]; }
    else       { s = d = e - E; g_deg[d] = 0; }   // reset for next launch
    int pos = atomicAdd(&g_cursor[d], 1);
    g_csr_src[pos] = s;
}

// ---------------- GEMM1 [N,256]x[256,256] + fused alpha1 --------------------
// 128x128 tile, BK=16, 256 threads, 8x8 per thread
#define G1_BM 128
#define G1_BN 128
#define G1_BK 16

__global__ __launch_bounds__(256, 2)
void k_gemm1(const float* __restrict__ A, const float* __restrict__ B,
             const float* __restrict__ att_s, const float* __restrict__ att_d,
             int M) {
    __shared__ float As[G1_BK][G1_BM + 4];   // transposed A tile
    __shared__ float Bs[G1_BK][G1_BN + 4];
    int tid = threadIdx.x;
    int tx = tid & 15;        // col group (8 cols each)
    int ty = tid >> 4;        // row group (8 rows each)
    int rowBase = blockIdx.y * G1_BM;
    int colBase = blockIdx.x * G1_BN;
    float acc[8][8] = {};
    for (int k0 = 0; k0 < IN_DIM; k0 += G1_BK) {
        // A tile: 128 rows x 16 cols, store transposed
#pragma unroll
        for (int i = 0; i < 2; i++) {
            int f = tid + i * 256;            // 0..511
            int r = f >> 2, c4 = f & 3;
            int gr = rowBase + r;
            float4 v = make_float4(0.f, 0.f, 0.f, 0.f);
            if (gr < M) v = *(const float4*)&A[gr * IN_DIM + k0 + c4 * 4];
            As[c4 * 4 + 0][r] = v.x;
            As[c4 * 4 + 1][r] = v.y;
            As[c4 * 4 + 2][r] = v.z;
            As[c4 * 4 + 3][r] = v.w;
        }
        // B tile: 16 rows x 128 cols
#pragma unroll
        for (int i = 0; i < 2; i++) {
            int f = tid + i * 256;            // 0..511
            int r = f >> 5, c4 = f & 31;
            *(float4*)&Bs[r][c4 * 4] =
                *(const float4*)&B[(k0 + r) * H1_DIM + colBase + c4 * 4];
        }
        __syncthreads();
#pragma unroll
        for (int k = 0; k < G1_BK; k++) {
            float4 a0 = *(const float4*)&As[k][ty * 8];
            float4 a1 = *(const float4*)&As[k][ty * 8 + 4];
            float4 b0 = *(const float4*)&Bs[k][tx * 8];
            float4 b1 = *(const float4*)&Bs[k][tx * 8 + 4];
            float a[8] = {a0.x, a0.y, a0.z, a0.w, a1.x, a1.y, a1.z, a1.w};
            float b[8] = {b0.x, b0.y, b0.z, b0.w, b1.x, b1.y, b1.z, b1.w};
#pragma unroll
            for (int i = 0; i < 8; i++)
#pragma unroll
                for (int j = 0; j < 8; j++)
                    acc[i][j] = fmaf(a[i], b[j], acc[i][j]);
        }
        __syncthreads();
    }
    // store h1
#pragma unroll
    for (int i = 0; i < 8; i++) {
        int gr = rowBase + ty * 8 + i;
        if (gr < M) {
            *(float4*)&g_h1[gr * H1_DIM + colBase + tx * 8] =
                make_float4(acc[i][0], acc[i][1], acc[i][2], acc[i][3]);
            *(float4*)&g_h1[gr * H1_DIM + colBase + tx * 8 + 4] =
                make_float4(acc[i][4], acc[i][5], acc[i][6], acc[i][7]);
        }
    }
    // fused alpha1: this block covers 2 complete heads (cols colBase..+127)
    float attw_s[8], attw_d[8];
#pragma unroll
    for (int j = 0; j < 8; j++) {
        int col = colBase + tx * 8 + j;
        attw_s[j] = att_s[col];
        attw_d[j] = att_d[col];
    }
    int hg = (colBase >> 6) + (tx >> 3);
#pragma unroll
    for (int i = 0; i < 8; i++) {
        float ss = 0.f, sd = 0.f;
#pragma unroll
        for (int j = 0; j < 8; j++) {
            ss = fmaf(acc[i][j], attw_s[j], ss);
            sd = fmaf(acc[i][j], attw_d[j], sd);
        }
#pragma unroll
        for (int off = 1; off < 8; off <<= 1) {
            ss += __shfl_xor_sync(0xffffffffu, ss, off);
            sd += __shfl_xor_sync(0xffffffffu, sd, off);
        }
        if ((tx & 7) == 0) {
            int row = rowBase + ty * 8 + i;
            if (row < M) {
                g_as1[row * HEADS + hg] = ss;
                g_ad1[row * HEADS + hg] = sd;
            }
        }
    }
}

// ---- fused L1 single-pass softmax + aggregate + bias + relu (block/dst) ----
__global__ void k_agg1(const float* __restrict__ bias) {
    int n = blockIdx.x;
    int tid = threadIdx.x;
    int beg = g_rowptr[n];
    int deg = g_rowptr[n + 1] - beg;
    int lane = tid & 31, warp = tid >> 5;

    __shared__ int    sh_src[64];
    __shared__ float  sh_w[HEADS][64];
    __shared__ float4 sh_s[8];
    __shared__ float  sh_inv[HEADS];
    __shared__ float  sh_red[4][H1_DIM];

    float4 ad4 = *(const float4*)&g_ad1[n * HEADS];

    int g = tid >> 6, c4 = tid & 63, head = c4 >> 4;
    float4 acc = make_float4(0.f, 0.f, 0.f, 0.f);
    float4 sacc = make_float4(0.f, 0.f, 0.f, 0.f);

    for (int base = 0; base < deg; base += 64) {
        int len = min(64, deg - base);
        __syncthreads();
        if (tid < len) {
            int src = g_csr_src[beg + base + tid];
            sh_src[tid] = src;
            float4 as = *(const float4*)&g_as1[src * HEADS];
            float e0 = __expf(lrelu(as.x + ad4.x));
            float e1 = __expf(lrelu(as.y + ad4.y));
            float e2 = __expf(lrelu(as.z + ad4.z));
            float e3 = __expf(lrelu(as.w + ad4.w));
            sh_w[0][tid] = e0; sh_w[1][tid] = e1;
            sh_w[2][tid] = e2; sh_w[3][tid] = e3;
            sacc.x += e0; sacc.y += e1; sacc.z += e2; sacc.w += e3;
        }
        __syncthreads();
        for (int k = g; k < len; k += 4) {
            float w = sh_w[head][k];
            float4 v = *(const float4*)&g_h1[sh_src[k] * H1_DIM + c4 * 4];
            acc.x = fmaf(w, v.x, acc.x);
            acc.y = fmaf(w, v.y, acc.y);
            acc.z = fmaf(w, v.z, acc.z);
            acc.w = fmaf(w, v.w, acc.w);
        }
    }
    // reduce denominator
#pragma unroll
    for (int off = 16; off > 0; off >>= 1) {
        sacc.x += __shfl_xor_sync(0xffffffffu, sacc.x, off);
        sacc.y += __shfl_xor_sync(0xffffffffu, sacc.y, off);
        sacc.z += __shfl_xor_sync(0xffffffffu, sacc.z, off);
        sacc.w += __shfl_xor_sync(0xffffffffu, sacc.w, off);
    }
    if (lane == 0) sh_s[warp] = sacc;
    __syncthreads();
    if (tid == 0) {
        float4 s = sh_s[0];
#pragma unroll
        for (int w = 1; w < 8; w++) {
            s.x += sh_s[w].x; s.y += sh_s[w].y;
            s.z += sh_s[w].z; s.w += sh_s[w].w;
        }
        sh_inv[0] = 1.f / s.x; sh_inv[1] = 1.f / s.y;
        sh_inv[2] = 1.f / s.z; sh_inv[3] = 1.f / s.w;
    }
    *(float4*)&sh_red[g][c4 * 4] = acc;
    __syncthreads();
    int c = tid;
    float v = (sh_red[0][c] + sh_red[1][c] + sh_red[2][c] + sh_red[3][c])
              * sh_inv[c >> 6] + bias[c];
    g_out1[n * H1_DIM + c] = v > 0.f ? v : 0.f;
}

// ---------------- GEMM2 [N,256]x[256,40] + fused alpha2 ---------------------
__global__ void k_gemm2(const float* __restrict__ W2,
                        const float* __restrict__ att_s,
                        const float* __restrict__ att_d, int M) {
    __shared__ float W2s[64 * OUT_DIM];
    __shared__ float hr[32 * 64];
    __shared__ float sh_o[32 * OUT_DIM];
    int tid = threadIdx.x;
    int rowBase = blockIdx.x * 32;
    float acc[5] = {0.f, 0.f, 0.f, 0.f, 0.f};
    for (int k0 = 0; k0 < H1_DIM; k0 += 64) {
        for (int idx = tid; idx < 64 * OUT_DIM; idx += 256)
            W2s[idx] = W2[(k0 + idx / OUT_DIM) * OUT_DIM + idx % OUT_DIM];
        for (int f = tid; f < 512; f += 256) {
            int r = f >> 4, c4 = f & 15;
            int row = rowBase + r;
            float4 v = make_float4(0.f, 0.f, 0.f, 0.f);
            if (row < M) v = *(const float4*)&g_out1[row * H1_DIM + k0 + c4 * 4];
            *(float4*)&hr[r * 64 + c4 * 4] = v;
        }
        __syncthreads();
#pragma unroll
        for (int oi = 0; oi < 5; oi++) {
            int out_idx = tid + oi * 256;
            int r = out_idx / OUT_DIM, c = out_idx % OUT_DIM;
            float a = acc[oi];
#pragma unroll 8
            for (int k = 0; k < 64; k++)
                a = fmaf(hr[r * 64 + k], W2s[k * OUT_DIM + c], a);
            acc[oi] = a;
        }
        __syncthreads();
    }
#pragma unroll
    for (int oi = 0; oi < 5; oi++) {
        int out_idx = tid + oi * 256;
        int r = out_idx / OUT_DIM, c = out_idx % OUT_DIM;
        int row = rowBase + r;
        sh_o[out_idx] = acc[oi];
        if (row < M) g_h2[row * OUT_DIM + c] = acc[oi];
    }
    __syncthreads();
    if (tid < 32) {
        int row = rowBase + tid;
        if (row < M) {
            float ss = 0.f, sd = 0.f;
#pragma unroll
            for (int k = 0; k < OUT_DIM; k++) {
                float v = sh_o[tid * OUT_DIM + k];
                ss = fmaf(v, att_s[k], ss);
                sd = fmaf(v, att_d[k], sd);
            }
            g_as2[row] = ss;
            g_ad2[row] = sd;
        }
    }
}

// ---- fused L2 single-pass softmax + aggregate + bias + log_softmax ---------
__global__ void k_agg2(const float* __restrict__ bias, float* __restrict__ out) {
    int n = blockIdx.x;
    int tid = threadIdx.x;
    int beg = g_rowptr[n];
    int deg = g_rowptr[n + 1] - beg;
    int lane = tid & 31, warp = tid >> 5;

    __shared__ int   sh_src[64];
    __shared__ float sh_w[64];
    __shared__ float sh_s[4];
    __shared__ float sh_inv;
    __shared__ float sh_part[128];
    __shared__ float sh_row[OUT_DIM];
    __shared__ float sh_lse;

    float adn = g_ad2[n];

    int eo = tid >> 6, c = tid & 63;
    float acc = 0.f, sacc = 0.f;
    for (int base = 0; base < deg; base += 64) {
        int len = min(64, deg - base);
        __syncthreads();
        if (tid < len) {
            int src = g_csr_src[beg + base + tid];
            sh_src[tid] = src;
            float e = __expf(lrelu(g_as2[src] + adn));
            sh_w[tid] = e;
            sacc += e;
        }
        __syncthreads();
        if (c < OUT_DIM) {
            for (int k = eo; k < len; k += 2)
                acc = fmaf(sh_w[k], g_h2[sh_src[k] * OUT_DIM + c], acc);
        }
    }
#pragma unroll
    for (int off = 16; off > 0; off >>= 1)
        sacc += __shfl_xor_sync(0xffffffffu, sacc, off);
    if (lane == 0) sh_s[warp] = sacc;
    sh_part[tid] = acc;
    __syncthreads();
    if (tid == 0) sh_inv = 1.f / (sh_s[0] + sh_s[1] + sh_s[2] + sh_s[3]);
    __syncthreads();
    if (tid < OUT_DIM)
        sh_row[tid] = (sh_part[tid] + sh_part[tid + 64]) * sh_inv + bias[tid];
    __syncthreads();
    if (tid == 0) {
        float m = -1e30f;
#pragma unroll
        for (int k = 0; k < OUT_DIM; k++) m = fmaxf(m, sh_row[k]);
        float s = 0.f;
#pragma unroll
        for (int k = 0; k < OUT_DIM; k++) s += __expf(sh_row[k] - m);
        sh_lse = m + logf(s);
    }
    __syncthreads();
    if (tid < OUT_DIM) out[n * OUT_DIM + tid] = sh_row[tid] - sh_lse;
}

// ----------------------------------------------------------------------------
extern "C" void kernel_launch(void* const* d_in, const int* in_sizes, int n_in,
                              void* d_out, int out_size) {
    const float* x   = (const float*)d_in[0];
    const int*   ei  = (const int*)d_in[1];
    const float* W1  = (const float*)d_in[2];
    const float* as1 = (const float*)d_in[3];
    const float* ad1 = (const float*)d_in[4];
    const float* b1  = (const float*)d_in[5];
    const float* W2  = (const float*)d_in[6];
    const float* as2 = (const float*)d_in[7];
    const float* ad2 = (const float*)d_in[8];
    const float* b2  = (const float*)d_in[9];
    float* out = (float*)d_out;

    int N  = in_sizes[0] / IN_DIM;
    int E  = in_sizes[1] / 2;
    int ET = E + N;

    // CSR build (g_deg is zero: static init on first run, k_scatter resets after)
    k_deg<<<(E + 255) / 256, 256>>>(ei, E);
    k_scan<<<1, 1024>>>(N);
    k_scatter<<<(ET + 255) / 256, 256>>>(ei, E, ET);

    // layer 1
    {
        dim3 grid(H1_DIM / G1_BN, (N + G1_BM - 1) / G1_BM);
        k_gemm1<<<grid, 256>>>(x, W1, as1, ad1, N);
    }
    k_agg1<<<N, 256>>>(b1);

    // layer 2
    k_gemm2<<<(N + 31) / 32, 256>>>(W2, as2, ad2, N);
    k_agg2<<<N, 128>>>(b2, out);
}

// round 6
// speedup vs baseline: 2.6899x; 1.0705x over previous
#include <cuda_runtime.h>
#include <cuda_bf16.h>
#include <math.h>
#include <stdint.h>

// ----------------------------------------------------------------------------
// SimpleGAT R6: tf32 tensor-core GEMM1 (3xTF32) + fused epilogues (from R5).
// ----------------------------------------------------------------------------

#define MAXN 10000
#define MAXE 320000
#define MAXET (MAXE + MAXN)

#define IN_DIM 256
#define H1_DIM 256
#define HEADS 4
#define HID 64
#define OUT_DIM 40

// ------------------------------ scratch ------------------------------------
__device__ __align__(16) float g_h1[MAXN * H1_DIM];
__device__ __align__(16) float g_out1[MAXN * H1_DIM];
__device__ __align__(16) float g_as1[MAXN * HEADS];
__device__ __align__(16) float g_ad1[MAXN * HEADS];

__device__ __align__(16) float g_h2[MAXN * OUT_DIM];
__device__ float g_as2[MAXN];
__device__ float g_ad2[MAXN];

__device__ int g_deg[MAXN];        // static-zero; re-zeroed by k_scatter each run
__device__ int g_rowptr[MAXN + 1];
__device__ int g_cursor[MAXN];
__device__ int g_csr_src[MAXET];

__device__ __forceinline__ float lrelu(float t) { return t > 0.f ? t : 0.2f * t; }

__device__ __forceinline__ uint32_t f2tf32(float x) {
    uint32_t r;
    asm("cvt.rna.tf32.f32 %0, %1;" : "=r"(r) : "f"(x));
    return r;
}

__device__ __forceinline__ void mma_tf32(float c[4], uint32_t a0, uint32_t a1,
                                         uint32_t a2, uint32_t a3,
                                         uint32_t b0, uint32_t b1) {
    asm volatile(
        "mma.sync.aligned.m16n8k8.row.col.f32.tf32.tf32.f32 "
        "{%0,%1,%2,%3}, {%4,%5,%6,%7}, {%8,%9}, {%0,%1,%2,%3};"
        : "+f"(c[0]), "+f"(c[1]), "+f"(c[2]), "+f"(c[3])
        : "r"(a0), "r"(a1), "r"(a2), "r"(a3), "r"(b0), "r"(b1));
}

// ------------------------------ CSR build -----------------------------------
__global__ void k_deg(const int* __restrict__ ei, int E) {
    int e = blockIdx.x * blockDim.x + threadIdx.x;
    if (e < E) atomicAdd(&g_deg[ei[E + e]], 1);
}

__global__ void k_scan(int N) {
    int tid = threadIdx.x;
    const int C = (N + 1023) >> 10;
    int start = tid * C;
    int local[16];
    int sum = 0;
#pragma unroll
    for (int j = 0; j < 16; j++) {
        if (j >= C) break;
        int i = start + j;
        int v = (i < N) ? (g_deg[i] + 1) : 0;   // +1 self loop
        local[j] = sum;
        sum += v;
    }
    int lane = tid & 31, warp = tid >> 5;
    int inc = sum;
#pragma unroll
    for (int off = 1; off < 32; off <<= 1) {
        int t = __shfl_up_sync(0xffffffffu, inc, off);
        if (lane >= off) inc += t;
    }
    __shared__ int wtot[32];
    if (lane == 31) wtot[warp] = inc;
    __syncthreads();
    if (warp == 0) {
        int v = wtot[lane];
#pragma unroll
        for (int off = 1; off < 32; off <<= 1) {
            int t = __shfl_up_sync(0xffffffffu, v, off);
            if (lane >= off) v += t;
        }
        wtot[lane] = v;
    }
    __syncthreads();
    int carry = (warp > 0 ? wtot[warp - 1] : 0) + (inc - sum);
#pragma unroll
    for (int j = 0; j < 16; j++) {
        if (j >= C) break;
        int i = start + j;
        if (i < N) {
            int e = carry + local[j];
            g_rowptr[i] = e;
            g_cursor[i] = e;
        }
    }
    if (tid == 1023) g_rowptr[N] = wtot[31];
}

__global__ void k_scatter(const int* __restrict__ ei, int E, int ET) {
    int e = blockIdx.x * blockDim.x + threadIdx.x;
    if (e >= ET) return;
    int s, d;
    if (e < E) { s = ei[e]; d = ei[E + e]; }
    else       { s = d = e - E; g_deg[d] = 0; }   // reset for next launch
    int pos = atomicAdd(&g_cursor[d], 1);
    g_csr_src[pos] = s;
}

// ---------------- GEMM1 [N,256]x[256,256] tf32 MMA + fused alpha1 -----------
// tile 128x128, BK=16, 8 warps (4 m x 2 n), warp tile 32x64
#define APAD 20
#define BPAD 136

__global__ __launch_bounds__(256, 2)
void k_gemm1(const float* __restrict__ A, const float* __restrict__ B,
             const float* __restrict__ att_s, const float* __restrict__ att_d,
             int M) {
    __shared__ uint32_t As_hi[128][APAD], As_lo[128][APAD];
    __shared__ uint32_t Bs_hi[16][BPAD], Bs_lo[16][BPAD];

    int tid = threadIdx.x;
    int lane = tid & 31, warp = tid >> 5;
    int warp_m = warp & 3, warp_n = warp >> 2;
    int groupID = lane >> 2, tid4 = lane & 3;
    int rowBase = blockIdx.y * 128;
    int colBase = blockIdx.x * 128;

    float acc[2][8][4] = {};

    for (int k0 = 0; k0 < IN_DIM; k0 += 16) {
        // load A tile (128 x 16) with hi/lo split
#pragma unroll
        for (int i = 0; i < 2; i++) {
            int f = tid + i * 256;            // 0..511
            int r = f >> 2, c4 = f & 3;
            int gr = rowBase + r;
            float4 v = make_float4(0.f, 0.f, 0.f, 0.f);
            if (gr < M) v = *(const float4*)&A[gr * IN_DIM + k0 + c4 * 4];
            uint32_t h0 = f2tf32(v.x), h1 = f2tf32(v.y),
                     h2 = f2tf32(v.z), h3 = f2tf32(v.w);
            uint32_t l0 = f2tf32(v.x - __uint_as_float(h0));
            uint32_t l1 = f2tf32(v.y - __uint_as_float(h1));
            uint32_t l2 = f2tf32(v.z - __uint_as_float(h2));
            uint32_t l3 = f2tf32(v.w - __uint_as_float(h3));
            *(uint4*)&As_hi[r][c4 * 4] = make_uint4(h0, h1, h2, h3);
            *(uint4*)&As_lo[r][c4 * 4] = make_uint4(l0, l1, l2, l3);
        }
        // load B tile (16 x 128)
#pragma unroll
        for (int i = 0; i < 2; i++) {
            int f = tid + i * 256;            // 0..511
            int r = f >> 5, c4 = f & 31;
            float4 v = *(const float4*)&B[(k0 + r) * H1_DIM + colBase + c4 * 4];
            uint32_t h0 = f2tf32(v.x), h1 = f2tf32(v.y),
                     h2 = f2tf32(v.z), h3 = f2tf32(v.w);
            uint32_t l0 = f2tf32(v.x - __uint_as_float(h0));
            uint32_t l1 = f2tf32(v.y - __uint_as_float(h1));
            uint32_t l2 = f2tf32(v.z - __uint_as_float(h2));
            uint32_t l3 = f2tf32(v.w - __uint_as_float(h3));
            *(uint4*)&Bs_hi[r][c4 * 4] = make_uint4(h0, h1, h2, h3);
            *(uint4*)&Bs_lo[r][c4 * 4] = make_uint4(l0, l1, l2, l3);
        }
        __syncthreads();

#pragma unroll
        for (int kk = 0; kk < 2; kk++) {
            int kc0 = kk * 8;
            uint32_t ah[2][4], al[2][4];
#pragma unroll
            for (int mt = 0; mt < 2; mt++) {
                int row = warp_m * 32 + mt * 16 + groupID;
                ah[mt][0] = As_hi[row][kc0 + tid4];
                ah[mt][1] = As_hi[row + 8][kc0 + tid4];
                ah[mt][2] = As_hi[row][kc0 + tid4 + 4];
                ah[mt][3] = As_hi[row + 8][kc0 + tid4 + 4];
                al[mt][0] = As_lo[row][kc0 + tid4];
                al[mt][1] = As_lo[row + 8][kc0 + tid4];
                al[mt][2] = As_lo[row][kc0 + tid4 + 4];
                al[mt][3] = As_lo[row + 8][kc0 + tid4 + 4];
            }
#pragma unroll
            for (int nt = 0; nt < 8; nt++) {
                int n = warp_n * 64 + nt * 8 + groupID;
                uint32_t bh0 = Bs_hi[kc0 + tid4][n];
                uint32_t bh1 = Bs_hi[kc0 + tid4 + 4][n];
                uint32_t bl0 = Bs_lo[kc0 + tid4][n];
                uint32_t bl1 = Bs_lo[kc0 + tid4 + 4][n];
#pragma unroll
                for (int mt = 0; mt < 2; mt++) {
                    mma_tf32(acc[mt][nt], ah[mt][0], ah[mt][1], ah[mt][2], ah[mt][3], bh0, bh1);
                    mma_tf32(acc[mt][nt], al[mt][0], al[mt][1], al[mt][2], al[mt][3], bh0, bh1);
                    mma_tf32(acc[mt][nt], ah[mt][0], ah[mt][1], ah[mt][2], ah[mt][3], bl0, bl1);
                }
            }
        }
        __syncthreads();
    }

    // ---- store h1 + fused alpha1 ----
    int head = (colBase >> 6) + warp_n;     // this warp's 64 cols = one head
    float ss[2][2] = {}, sd[2][2] = {};     // [mt][half]
#pragma unroll
    for (int mt = 0; mt < 2; mt++) {
        int row0 = rowBase + warp_m * 32 + mt * 16 + groupID;
        int row1 = row0 + 8;
#pragma unroll
        for (int nt = 0; nt < 8; nt++) {
            int col = colBase + warp_n * 64 + nt * 8 + tid4 * 2;
            float a_s0 = att_s[col], a_s1 = att_s[col + 1];
            float a_d0 = att_d[col], a_d1 = att_d[col + 1];
            float c0 = acc[mt][nt][0], c1 = acc[mt][nt][1];
            float c2 = acc[mt][nt][2], c3 = acc[mt][nt][3];
            if (row0 < M) *(float2*)&g_h1[row0 * H1_DIM + col] = make_float2(c0, c1);
            if (row1 < M) *(float2*)&g_h1[row1 * H1_DIM + col] = make_float2(c2, c3);
            ss[mt][0] = fmaf(c0, a_s0, fmaf(c1, a_s1, ss[mt][0]));
            ss[mt][1] = fmaf(c2, a_s0, fmaf(c3, a_s1, ss[mt][1]));
            sd[mt][0] = fmaf(c0, a_d0, fmaf(c1, a_d1, sd[mt][0]));
            sd[mt][1] = fmaf(c2, a_d0, fmaf(c3, a_d1, sd[mt][1]));
        }
    }
    // reduce across the quad (lanes sharing a row)
#pragma unroll
    for (int mt = 0; mt < 2; mt++)
#pragma unroll
        for (int hf = 0; hf < 2; hf++) {
#pragma unroll
            for (int off = 1; off < 4; off <<= 1) {
                ss[mt][hf] += __shfl_xor_sync(0xffffffffu, ss[mt][hf], off);
                sd[mt][hf] += __shfl_xor_sync(0xffffffffu, sd[mt][hf], off);
            }
            if (tid4 == 0) {
                int row = rowBase + warp_m * 32 + mt * 16 + groupID + hf * 8;
                if (row < M) {
                    g_as1[row * HEADS + head] = ss[mt][hf];
                    g_ad1[row * HEADS + head] = sd[mt][hf];
                }
            }
        }
}

// ---- fused L1 single-pass softmax + aggregate + bias + relu (block/dst) ----
__global__ void k_agg1(const float* __restrict__ bias) {
    int n = blockIdx.x;
    int tid = threadIdx.x;
    int beg = g_rowptr[n];
    int deg = g_rowptr[n + 1] - beg;
    int lane = tid & 31, warp = tid >> 5;

    __shared__ int    sh_src[64];
    __shared__ float  sh_w[HEADS][64];
    __shared__ float4 sh_s[8];
    __shared__ float  sh_inv[HEADS];
    __shared__ float  sh_red[4][H1_DIM];

    float4 ad4 = *(const float4*)&g_ad1[n * HEADS];

    int g = tid >> 6, c4 = tid & 63, head = c4 >> 4;
    float4 acc = make_float4(0.f, 0.f, 0.f, 0.f);
    float4 sacc = make_float4(0.f, 0.f, 0.f, 0.f);

    for (int base = 0; base < deg; base += 64) {
        int len = min(64, deg - base);
        __syncthreads();
        if (tid < len) {
            int src = g_csr_src[beg + base + tid];
            sh_src[tid] = src;
            float4 as = *(const float4*)&g_as1[src * HEADS];
            float e0 = __expf(lrelu(as.x + ad4.x));
            float e1 = __expf(lrelu(as.y + ad4.y));
            float e2 = __expf(lrelu(as.z + ad4.z));
            float e3 = __expf(lrelu(as.w + ad4.w));
            sh_w[0][tid] = e0; sh_w[1][tid] = e1;
            sh_w[2][tid] = e2; sh_w[3][tid] = e3;
            sacc.x += e0; sacc.y += e1; sacc.z += e2; sacc.w += e3;
        }
        __syncthreads();
        for (int k = g; k < len; k += 4) {
            float w = sh_w[head][k];
            float4 v = *(const float4*)&g_h1[sh_src[k] * H1_DIM + c4 * 4];
            acc.x = fmaf(w, v.x, acc.x);
            acc.y = fmaf(w, v.y, acc.y);
            acc.z = fmaf(w, v.z, acc.z);
            acc.w = fmaf(w, v.w, acc.w);
        }
    }
#pragma unroll
    for (int off = 16; off > 0; off >>= 1) {
        sacc.x += __shfl_xor_sync(0xffffffffu, sacc.x, off);
        sacc.y += __shfl_xor_sync(0xffffffffu, sacc.y, off);
        sacc.z += __shfl_xor_sync(0xffffffffu, sacc.z, off);
        sacc.w += __shfl_xor_sync(0xffffffffu, sacc.w, off);
    }
    if (lane == 0) sh_s[warp] = sacc;
    __syncthreads();
    if (tid == 0) {
        float4 s = sh_s[0];
#pragma unroll
        for (int w = 1; w < 8; w++) {
            s.x += sh_s[w].x; s.y += sh_s[w].y;
            s.z += sh_s[w].z; s.w += sh_s[w].w;
        }
        sh_inv[0] = 1.f / s.x; sh_inv[1] = 1.f / s.y;
        sh_inv[2] = 1.f / s.z; sh_inv[3] = 1.f / s.w;
    }
    *(float4*)&sh_red[g][c4 * 4] = acc;
    __syncthreads();
    int c = tid;
    float v = (sh_red[0][c] + sh_red[1][c] + sh_red[2][c] + sh_red[3][c])
              * sh_inv[c >> 6] + bias[c];
    g_out1[n * H1_DIM + c] = v > 0.f ? v : 0.f;
}

// ---------------- GEMM2 [N,256]x[256,40] + fused alpha2 ---------------------
__global__ void k_gemm2(const float* __restrict__ W2,
                        const float* __restrict__ att_s,
                        const float* __restrict__ att_d, int M) {
    __shared__ float W2s[64 * OUT_DIM];
    __shared__ float hr[32 * 64];
    __shared__ float sh_o[32 * OUT_DIM];
    int tid = threadIdx.x;
    int rowBase = blockIdx.x * 32;
    float acc[5] = {0.f, 0.f, 0.f, 0.f, 0.f};
    for (int k0 = 0; k0 < H1_DIM; k0 += 64) {
        for (int idx = tid; idx < 64 * OUT_DIM; idx += 256)
            W2s[idx] = W2[(k0 + idx / OUT_DIM) * OUT_DIM + idx % OUT_DIM];
        for (int f = tid; f < 512; f += 256) {
            int r = f >> 4, c4 = f & 15;
            int row = rowBase + r;
            float4 v = make_float4(0.f, 0.f, 0.f, 0.f);
            if (row < M) v = *(const float4*)&g_out1[row * H1_DIM + k0 + c4 * 4];
            *(float4*)&hr[r * 64 + c4 * 4] = v;
        }
        __syncthreads();
#pragma unroll
        for (int oi = 0; oi < 5; oi++) {
            int out_idx = tid + oi * 256;
            int r = out_idx / OUT_DIM, c = out_idx % OUT_DIM;
            float a = acc[oi];
#pragma unroll 8
            for (int k = 0; k < 64; k++)
                a = fmaf(hr[r * 64 + k], W2s[k * OUT_DIM + c], a);
            acc[oi] = a;
        }
        __syncthreads();
    }
#pragma unroll
    for (int oi = 0; oi < 5; oi++) {
        int out_idx = tid + oi * 256;
        int r = out_idx / OUT_DIM, c = out_idx % OUT_DIM;
        int row = rowBase + r;
        sh_o[out_idx] = acc[oi];
        if (row < M) g_h2[row * OUT_DIM + c] = acc[oi];
    }
    __syncthreads();
    if (tid < 32) {
        int row = rowBase + tid;
        if (row < M) {
            float ss = 0.f, sd = 0.f;
#pragma unroll
            for (int k = 0; k < OUT_DIM; k++) {
                float v = sh_o[tid * OUT_DIM + k];
                ss = fmaf(v, att_s[k], ss);
                sd = fmaf(v, att_d[k], sd);
            }
            g_as2[row] = ss;
            g_ad2[row] = sd;
        }
    }
}

// ---- fused L2 single-pass softmax + aggregate + bias + log_softmax ---------
__global__ void k_agg2(const float* __restrict__ bias, float* __restrict__ out) {
    int n = blockIdx.x;
    int tid = threadIdx.x;
    int beg = g_rowptr[n];
    int deg = g_rowptr[n + 1] - beg;
    int lane = tid & 31, warp = tid >> 5;

    __shared__ int   sh_src[64];
    __shared__ float sh_w[64];
    __shared__ float sh_s[4];
    __shared__ float sh_inv;
    __shared__ float sh_part[128];
    __shared__ float sh_row[OUT_DIM];
    __shared__ float sh_lse;

    float adn = g_ad2[n];

    int eo = tid >> 6, c = tid & 63;
    float acc = 0.f, sacc = 0.f;
    for (int base = 0; base < deg; base += 64) {
        int len = min(64, deg - base);
        __syncthreads();
        if (tid < len) {
            int src = g_csr_src[beg + base + tid];
            sh_src[tid] = src;
            float e = __expf(lrelu(g_as2[src] + adn));
            sh_w[tid] = e;
            sacc += e;
        }
        __syncthreads();
        if (c < OUT_DIM) {
            for (int k = eo; k < len; k += 2)
                acc = fmaf(sh_w[k], g_h2[sh_src[k] * OUT_DIM + c], acc);
        }
    }
#pragma unroll
    for (int off = 16; off > 0; off >>= 1)
        sacc += __shfl_xor_sync(0xffffffffu, sacc, off);
    if (lane == 0) sh_s[warp] = sacc;
    sh_part[tid] = acc;
    __syncthreads();
    if (tid == 0) sh_inv = 1.f / (sh_s[0] + sh_s[1] + sh_s[2] + sh_s[3]);
    __syncthreads();
    if (tid < OUT_DIM)
        sh_row[tid] = (sh_part[tid] + sh_part[tid + 64]) * sh_inv + bias[tid];
    __syncthreads();
    if (tid == 0) {
        float m = -1e30f;
#pragma unroll
        for (int k = 0; k < OUT_DIM; k++) m = fmaxf(m, sh_row[k]);
        float s = 0.f;
#pragma unroll
        for (int k = 0; k < OUT_DIM; k++) s += __expf(sh_row[k] - m);
        sh_lse = m + logf(s);
    }
    __syncthreads();
    if (tid < OUT_DIM) out[n * OUT_DIM + tid] = sh_row[tid] - sh_lse;
}

// ----------------------------------------------------------------------------
extern "C" void kernel_launch(void* const* d_in, const int* in_sizes, int n_in,
                              void* d_out, int out_size) {
    const float* x   = (const float*)d_in[0];
    const int*   ei  = (const int*)d_in[1];
    const float* W1  = (const float*)d_in[2];
    const float* as1 = (const float*)d_in[3];
    const float* ad1 = (const float*)d_in[4];
    const float* b1  = (const float*)d_in[5];
    const float* W2  = (const float*)d_in[6];
    const float* as2 = (const float*)d_in[7];
    const float* ad2 = (const float*)d_in[8];
    const float* b2  = (const float*)d_in[9];
    float* out = (float*)d_out;

    int N  = in_sizes[0] / IN_DIM;
    int E  = in_sizes[1] / 2;
    int ET = E + N;

    // CSR build
    k_deg<<<(E + 255) / 256, 256>>>(ei, E);
    k_scan<<<1, 1024>>>(N);
    k_scatter<<<(ET + 255) / 256, 256>>>(ei, E, ET);

    // layer 1
    {
        dim3 grid(H1_DIM / 128, (N + 127) / 128);
        k_gemm1<<<grid, 256>>>(x, W1, as1, ad1, N);
    }
    k_agg1<<<N, 256>>>(b1);

    // layer 2
    k_gemm2<<<(N + 31) / 32, 256>>>(W2, as2, ad2, N);
    k_agg2<<<N, 128>>>(b2, out);
}